// round 14
// baseline (speedup 1.0000x reference)
#include <cuda_runtime.h>
#include <math.h>

// ---------------------------------------------------------------------------
// Fast helpers
// ---------------------------------------------------------------------------
__device__ __forceinline__ float sqrt_approx(float x) {
    float r;
    asm("sqrt.approx.f32 %0, %1;" : "=f"(r) : "f"(x));
    return r;
}
__device__ __forceinline__ float ex2_approx(float x) {
    float r;
    asm("ex2.approx.f32 %0, %1;" : "=f"(r) : "f"(x));
    return r;
}
__device__ __forceinline__ float lg2_approx(float x) {
    float r;
    asm("lg2.approx.f32 %0, %1;" : "=f"(r) : "f"(x));
    return r;
}

// ---------------------------------------------------------------------------
// sRGB -> Lab
// ---------------------------------------------------------------------------
__device__ __forceinline__ float srgb_inv(float x) {
    float u = (x + 0.055f) * (1.0f / 1.055f);
    float p = ex2_approx(2.4f * lg2_approx(u));
    return (x > 0.04045f) ? p : x * (1.0f / 12.92f);
}

__device__ __forceinline__ float lab_f(float t) {
    float p = ex2_approx((1.0f / 3.0f) * lg2_approx(fmaxf(t, 1e-8f)));
    return (t > 0.008856f) ? p : fmaf(7.787f, t, 4.0f / 29.0f);
}

__device__ __forceinline__ void rgb2lab(float r, float g, float b,
                                        float& L, float& A, float& B) {
    r = srgb_inv(r);
    g = srgb_inv(g);
    b = srgb_inv(b);
    float x = 0.412453f * r + 0.35758f  * g + 0.180423f * b;
    float y = 0.212671f * r + 0.71516f  * g + 0.072169f * b;
    float z = 0.019334f * r + 0.119193f * g + 0.950227f * b;
    float fx = lab_f(x * (1.0f / 0.95047f));
    float fy = lab_f(y);
    float fz = lab_f(z * (1.0f / 1.08883f));
    L = 116.0f * fy - 16.0f;
    A = 500.0f * (fx - fy);
    B = 200.0f * (fy - fz);
}

// ---------------------------------------------------------------------------
// CIEDE2000 (returns deltaE / 100)
//  - hue terms via vector identities (no per-image atan2 / sincos / wraps)
//  - T weighting as exact bivariate polynomial P(c) + s*Q(c)
//  - dtheta Gaussian via cos(H-275deg) series (no atan2 at all)
// ---------------------------------------------------------------------------
__device__ __forceinline__ float ciede2000_div100(float L1, float a1, float b1,
                                                  float L2, float a2, float b2) {
    const float K25_7 = 6103515625.0f;  // 25^7

    float C1 = sqrt_approx(fmaf(a1, a1, b1 * b1));
    float C2 = sqrt_approx(fmaf(a2, a2, b2 * b2));
    float Cbar = 0.5f * (C1 + C2);
    float cb2 = Cbar * Cbar;
    float cb4 = cb2 * cb2;
    float c7  = cb4 * cb2 * Cbar;
    float G = 0.5f * (1.0f - sqrt_approx(__fdividef(c7, c7 + K25_7)));
    float scale = 1.0f + G;

    float a1p = a1 * scale;
    float a2p = a2 * scale;
    float C1p = sqrt_approx(fmaf(a1p, a1p, b1 * b1));
    float C2p = sqrt_approx(fmaf(a2p, a2p, b2 * b2));

    // L term
    float Lbar = 0.5f * (L1 + L2);
    float lt = (Lbar - 50.0f) * (Lbar - 50.0f);
    float SL = 1.0f + 0.015f * lt * rsqrtf(20.0f + lt);
    float L_term = __fdividef(L2 - L1, SL);

    // C term
    float Cbarp = 0.5f * (C1p + C2p);
    float SC = fmaf(0.045f, Cbarp, 1.0f);
    float C_term = __fdividef(C2p - C1p, SC);

    // Hue difference term: dH_term = 2*sqrt(CC)*sin(dH/2)
    float CC    = C1p * C2p;
    float dot   = fmaf(a1p, a2p, b1 * b2);   // CC * cos(h2-h1)
    float cross = fmaf(a1p, b2, -b1 * a2p);  // CC * sin(h2-h1)
    float dH_term = copysignf(sqrt_approx(2.0f * fmaxf(CC - dot, 0.0f)), cross);

    // Mean hue direction (short-arc bisector), w = C2p*v1 + C1p*v2
    float wx = fmaf(C2p, a1p, C1p * a2p);
    float wy = fmaf(C2p, b1,  C1p * b2);
    float rs = rsqrtf(fmaxf(fmaf(wx, wx, wy * wy), 1e-30f));
    float cH = wx * rs;
    float sH = wy * rs;

    // T = P(cH) + sH*Q(cH)   (exact expansion of the 4-cosine sum)
    float P = fmaf(fmaf(fmaf(fmaf(-0.72638480f, cH, 1.27298803f), cH,
                             1.20638480f), cH, -1.10196534f), cH, 0.66920190f);
    float Q = fmaf(fmaf(fmaf(-1.42561044f, cH, -0.13379643f), cH,
                        0.71280522f), cH, -0.05155090f);
    float T = fmaf(sH, Q, P);

    float SH = fmaf(0.015f * Cbarp, T, 1.0f);
    float H_term = __fdividef(dH_term, SH);

    // Rotation term
    float cp2 = Cbarp * Cbarp;
    float cp4 = cp2 * cp2;
    float c7p = cp4 * cp2 * Cbarp;
    float Rc = 2.0f * sqrt_approx(__fdividef(c7p, c7p + K25_7));

    // dtheta = pi/6 * exp(-((Hdeg-275)/25)^2), via delta = H - 275deg:
    //   cos(delta) = cH*cos275 + sH*sin275
    //   delta^2    = 2u + u^2/3 + (4/45)u^3,  u = 1 - cos(delta)
    float cd = fmaf(cH, 0.08715574f, -0.99619470f * sH);
    float u  = 1.0f - cd;
    float dsq = u * fmaf(u, fmaf(u, 0.08888889f, 0.33333333f), 2.0f);
    // 2*dtheta = (pi/3) * exp(-5.25249*dsq);  exp via ex2: *log2(e)
    float twodt = 1.04719755f * ex2_approx(-7.57774f * dsq);
    float R_term = -__sinf(twodt) * Rc * C_term * H_term;

    float dE2 = fmaf(L_term, L_term,
               fmaf(C_term, C_term,
               fmaf(H_term, H_term, R_term)));
    return sqrt_approx(fmaxf(dE2, 0.0f)) * 0.01f;
}

// ---------------------------------------------------------------------------
// Kernel: one thread = 4 pixels (float4), layout (B, 3, H, W)
// ---------------------------------------------------------------------------
constexpr int PLANE = 512 * 512;       // H*W (power of two)
constexpr int IMG_STRIDE = 3 * PLANE;  // per-batch stride in elements

__global__ void __launch_bounds__(256)
ciede2000_kernel(const float4* __restrict__ im1,
                 const float4* __restrict__ im2,
                 float4* __restrict__ out,
                 int nq)
{
    int v = blockIdx.x * 256 + threadIdx.x;
    if (v >= nq) return;

    int p   = v << 2;
    int n   = p / PLANE;
    int pix = p - n * PLANE;
    int b4  = (n * IMG_STRIDE + pix) >> 2;
    const int c4 = PLANE >> 2;

    float4 r1 = im1[b4];
    float4 g1 = im1[b4 + c4];
    float4 u1 = im1[b4 + 2 * c4];
    float4 r2 = im2[b4];
    float4 g2 = im2[b4 + c4];
    float4 u2 = im2[b4 + 2 * c4];

    float R1[4] = {r1.x, r1.y, r1.z, r1.w};
    float G1[4] = {g1.x, g1.y, g1.z, g1.w};
    float B1[4] = {u1.x, u1.y, u1.z, u1.w};
    float R2[4] = {r2.x, r2.y, r2.z, r2.w};
    float G2[4] = {g2.x, g2.y, g2.z, g2.w};
    float B2[4] = {u2.x, u2.y, u2.z, u2.w};

    float o[4];
#pragma unroll
    for (int j = 0; j < 4; j++) {
        float L1, A1, Bb1, L2, A2, Bb2;
        rgb2lab(R1[j], G1[j], B1[j], L1, A1, Bb1);
        rgb2lab(R2[j], G2[j], B2[j], L2, A2, Bb2);
        o[j] = ciede2000_div100(L1, A1, Bb1, L2, A2, Bb2);
    }

    out[v] = make_float4(o[0], o[1], o[2], o[3]);
}

// ---------------------------------------------------------------------------
// Launch
// ---------------------------------------------------------------------------
extern "C" void kernel_launch(void* const* d_in, const int* in_sizes, int n_in,
                              void* d_out, int out_size) {
    const float4* im1 = (const float4*)d_in[0];
    const float4* im2 = (const float4*)d_in[1];
    float4* out = (float4*)d_out;

    int nq = out_size >> 2;
    int blocks = (nq + 255) / 256;
    ciede2000_kernel<<<blocks, 256>>>(im1, im2, out, nq);
}

// round 15
// speedup vs baseline: 1.0639x; 1.0639x over previous
#include <cuda_runtime.h>
#include <math.h>

typedef unsigned long long u64;

// ---------------------------------------------------------------------------
// Packed 2xf32 helpers (Blackwell FFMA2 path — only reachable via PTX)
// ---------------------------------------------------------------------------
__device__ __forceinline__ u64 pk2(float lo, float hi) {
    u64 d; asm("mov.b64 %0, {%1, %2};" : "=l"(d) : "f"(lo), "f"(hi)); return d;
}
__device__ __forceinline__ void upk2(float& lo, float& hi, u64 d) {
    asm("mov.b64 {%0, %1}, %2;" : "=f"(lo), "=f"(hi) : "l"(d));
}
__device__ __forceinline__ u64 f2fma(u64 a, u64 b, u64 c) {
    u64 d; asm("fma.rn.f32x2 %0, %1, %2, %3;" : "=l"(d) : "l"(a), "l"(b), "l"(c)); return d;
}
__device__ __forceinline__ u64 f2mul(u64 a, u64 b) {
    u64 d; asm("mul.rn.f32x2 %0, %1, %2;" : "=l"(d) : "l"(a), "l"(b)); return d;
}
__device__ __forceinline__ u64 f2add(u64 a, u64 b) {
    u64 d; asm("add.rn.f32x2 %0, %1, %2;" : "=l"(d) : "l"(a), "l"(b)); return d;
}
__device__ __forceinline__ u64 f2neg(u64 a) { return a ^ 0x8000000080000000ULL; }
__device__ __forceinline__ u64 f2abs(u64 a) { return a & 0x7FFFFFFF7FFFFFFFULL; }
__device__ __forceinline__ u64 f2sub(u64 a, u64 b) { return f2add(a, f2neg(b)); }
__device__ __forceinline__ u64 f2copysign(u64 mag, u64 sgn) {
    return (mag & 0x7FFFFFFF7FFFFFFFULL) | (sgn & 0x8000000080000000ULL);
}

// Scalar MUFU applied per half
__device__ __forceinline__ float sqrt_approx(float x) {
    float r; asm("sqrt.approx.f32 %0, %1;" : "=f"(r) : "f"(x)); return r;
}
__device__ __forceinline__ float rsqrt_approx(float x) {
    float r; asm("rsqrt.approx.f32 %0, %1;" : "=f"(r) : "f"(x)); return r;
}
__device__ __forceinline__ float rcp_approx(float x) {
    float r; asm("rcp.approx.f32 %0, %1;" : "=f"(r) : "f"(x)); return r;
}
__device__ __forceinline__ float ex2_approx(float x) {
    float r; asm("ex2.approx.f32 %0, %1;" : "=f"(r) : "f"(x)); return r;
}
__device__ __forceinline__ float lg2_approx(float x) {
    float r; asm("lg2.approx.f32 %0, %1;" : "=f"(r) : "f"(x)); return r;
}
__device__ __forceinline__ u64 f2sqrt(u64 x) {
    float l, h; upk2(l, h, x);
    return pk2(sqrt_approx(l), sqrt_approx(h));
}
__device__ __forceinline__ u64 f2rsqrt(u64 x) {
    float l, h; upk2(l, h, x);
    return pk2(rsqrt_approx(l), rsqrt_approx(h));
}
__device__ __forceinline__ u64 f2rcp(u64 x) {
    float l, h; upk2(l, h, x);
    return pk2(rcp_approx(l), rcp_approx(h));
}
__device__ __forceinline__ u64 f2ex2(u64 x) {
    float l, h; upk2(l, h, x);
    return pk2(ex2_approx(l), ex2_approx(h));
}

// ---------------------------------------------------------------------------
// sRGB -> Lab (scalar: select/MUFU dominated)
// ---------------------------------------------------------------------------
__device__ __forceinline__ float srgb_inv(float x) {
    float u = (x + 0.055f) * (1.0f / 1.055f);
    float p = ex2_approx(2.4f * lg2_approx(u));
    return (x > 0.04045f) ? p : x * (1.0f / 12.92f);
}
__device__ __forceinline__ float lab_f(float t) {
    // t >= 0 guaranteed by input domain; lg2(0)=-inf -> ex2 -> 0, select safe
    float p = ex2_approx((1.0f / 3.0f) * lg2_approx(t));
    return (t > 0.008856f) ? p : fmaf(7.787f, t, 4.0f / 29.0f);
}
__device__ __forceinline__ void rgb2lab(float r, float g, float b,
                                        float& L, float& A, float& B) {
    r = srgb_inv(r);
    g = srgb_inv(g);
    b = srgb_inv(b);
    float x = 0.412453f * r + 0.35758f  * g + 0.180423f * b;
    float y = 0.212671f * r + 0.71516f  * g + 0.072169f * b;
    float z = 0.019334f * r + 0.119193f * g + 0.950227f * b;
    float fx = lab_f(x * (1.0f / 0.95047f));
    float fy = lab_f(y);
    float fz = lab_f(z * (1.0f / 1.08883f));
    L = 116.0f * fy - 16.0f;
    A = 500.0f * (fx - fy);
    B = 200.0f * (fy - fz);
}

// ---------------------------------------------------------------------------
// CIEDE2000 on a PIXEL PAIR, fully packed f32x2. Returns packed deltaE/100.
// ---------------------------------------------------------------------------
__device__ __forceinline__ u64 ciede_pair(u64 L1, u64 a1, u64 b1,
                                          u64 L2, u64 a2, u64 b2)
{
    const u64 HALF = pk2(0.5f, 0.5f);
    const u64 ONE  = pk2(1.0f, 1.0f);
    const u64 TWO  = pk2(2.0f, 2.0f);
    const u64 K7   = pk2(6103515625.0f, 6103515625.0f);   // 25^7
    const u64 EPSP = pk2(1e-18f, 1e-18f);

    u64 C1 = f2sqrt(f2fma(a1, a1, f2mul(b1, b1)));
    u64 C2 = f2sqrt(f2fma(a2, a2, f2mul(b2, b2)));
    u64 Cbar = f2mul(f2add(C1, C2), HALF);
    u64 cb2 = f2mul(Cbar, Cbar);
    u64 cb4 = f2mul(cb2, cb2);
    u64 c7  = f2mul(f2mul(cb4, cb2), Cbar);
    // sqrt(c7/(c7+K)) = c7 * rsqrt(c7*(c7+K) + eps)   (eps makes c7=0 -> 0)
    u64 sg = f2mul(c7, f2rsqrt(f2fma(c7, f2add(c7, K7), EPSP)));
    u64 scale = f2fma(sg, pk2(-0.5f, -0.5f), pk2(1.5f, 1.5f));  // 1 + G

    u64 a1p = f2mul(a1, scale);
    u64 a2p = f2mul(a2, scale);
    u64 C1p = f2sqrt(f2fma(a1p, a1p, f2mul(b1, b1)));
    u64 C2p = f2sqrt(f2fma(a2p, a2p, f2mul(b2, b2)));

    // SL
    u64 Lb50 = f2fma(f2add(L1, L2), HALF, pk2(-50.f, -50.f));
    u64 lt = f2mul(Lb50, Lb50);
    u64 SL = f2fma(f2mul(pk2(0.015f, 0.015f), lt),
                   f2rsqrt(f2add(pk2(20.f, 20.f), lt)), ONE);
    // SC
    u64 Cbarp = f2mul(f2add(C1p, C2p), HALF);
    u64 SC = f2fma(pk2(0.045f, 0.045f), Cbarp, ONE);

    // dH_term = copysign(sqrt(|2(CC - dot)|), cross)
    u64 CC    = f2mul(C1p, C2p);
    u64 dotp  = f2fma(a1p, a2p, f2mul(b1, b2));
    u64 cross = f2fma(a1p, b2, f2neg(f2mul(b1, a2p)));
    u64 dHt = f2copysign(f2sqrt(f2abs(f2mul(TWO, f2sub(CC, dotp)))), cross);

    // mean hue direction (short-arc bisector)
    u64 wx = f2fma(C2p, a1p, f2mul(C1p, a2p));
    u64 wy = f2fma(C2p, b1,  f2mul(C1p, b2));
    u64 rs = f2rsqrt(f2fma(wx, wx, f2fma(wy, wy, pk2(1e-30f, 1e-30f))));
    u64 cH = f2mul(wx, rs);
    u64 sH = f2mul(wy, rs);

    // T = P(cH) + sH*Q(cH)
    u64 P = f2fma(f2fma(f2fma(f2fma(pk2(-0.72638480f, -0.72638480f), cH,
                 pk2(1.27298803f, 1.27298803f)), cH,
                 pk2(1.20638480f, 1.20638480f)), cH,
                 pk2(-1.10196534f, -1.10196534f)), cH,
                 pk2(0.66920190f, 0.66920190f));
    u64 Q = f2fma(f2fma(f2fma(pk2(-1.42561044f, -1.42561044f), cH,
                 pk2(-0.13379643f, -0.13379643f)), cH,
                 pk2(0.71280522f, 0.71280522f)), cH,
                 pk2(-0.05155090f, -0.05155090f));
    u64 T = f2fma(sH, Q, P);
    u64 SH = f2fma(f2mul(pk2(0.015f, 0.015f), Cbarp), T, ONE);

    // combined reciprocal for the three denominators
    u64 SLSC = f2mul(SL, SC);
    u64 SLSH = f2mul(SL, SH);
    u64 SCSH = f2mul(SC, SH);
    u64 inv  = f2rcp(f2mul(SLSC, SH));
    u64 Lt = f2mul(f2mul(f2sub(L2, L1),  SCSH), inv);
    u64 Ct = f2mul(f2mul(f2sub(C2p, C1p), SLSH), inv);
    u64 Ht = f2mul(f2mul(dHt, SLSC), inv);

    // Rc/2 = c7p * rsqrt(c7p*(c7p+K) + eps)
    u64 cp2 = f2mul(Cbarp, Cbarp);
    u64 cp4 = f2mul(cp2, cp2);
    u64 c7p = f2mul(f2mul(cp4, cp2), Cbarp);
    u64 Rc2 = f2mul(c7p, f2rsqrt(f2fma(c7p, f2add(c7p, K7), EPSP)));

    // dtheta: cos(H-275deg) -> delta^2 series -> Gaussian via ex2
    u64 cd = f2fma(cH, pk2(0.08715574f, 0.08715574f),
                   f2mul(sH, pk2(-0.99619470f, -0.99619470f)));
    u64 uu = f2sub(ONE, cd);
    u64 dsq = f2mul(uu, f2fma(uu, f2fma(uu, pk2(0.08888889f, 0.08888889f),
                    pk2(0.33333333f, 0.33333333f)), TWO));
    u64 twodt = f2mul(pk2(1.04719755f, 1.04719755f),
                      f2ex2(f2mul(pk2(-7.57774f, -7.57774f), dsq)));
    // sin(x), x in (0, pi/3]: x*(1 + x2*(-1/6 + x2/120))
    u64 xx = f2mul(twodt, twodt);
    u64 sn = f2mul(twodt, f2fma(xx, f2fma(xx, pk2(0.00833333f, 0.00833333f),
                    pk2(-0.16666667f, -0.16666667f)), ONE));
    // R_term = -sin * 2*Rc2 * Ct * Ht
    u64 Rt = f2mul(f2mul(f2neg(f2mul(TWO, sn)), Rc2), f2mul(Ct, Ht));

    u64 dE2 = f2fma(Lt, Lt, f2fma(Ct, Ct, f2fma(Ht, Ht, Rt)));
    return f2mul(f2sqrt(f2abs(dE2)), pk2(0.01f, 0.01f));
}

// ---------------------------------------------------------------------------
// Kernel: one thread = 4 pixels = 2 packed pairs, layout (B, 3, H, W)
// ---------------------------------------------------------------------------
constexpr int PLANE = 512 * 512;
constexpr int IMG_STRIDE = 3 * PLANE;

__global__ void __launch_bounds__(256)
ciede2000_kernel(const float4* __restrict__ im1,
                 const float4* __restrict__ im2,
                 float4* __restrict__ out,
                 int nq)
{
    int v = blockIdx.x * 256 + threadIdx.x;
    if (v >= nq) return;

    int p   = v << 2;
    int n   = p / PLANE;
    int pix = p - n * PLANE;
    int b4  = (n * IMG_STRIDE + pix) >> 2;
    const int c4 = PLANE >> 2;

    float4 r1 = im1[b4];
    float4 g1 = im1[b4 + c4];
    float4 u1 = im1[b4 + 2 * c4];
    float4 r2 = im2[b4];
    float4 g2 = im2[b4 + c4];
    float4 u2 = im2[b4 + 2 * c4];

    float R1[4] = {r1.x, r1.y, r1.z, r1.w};
    float G1[4] = {g1.x, g1.y, g1.z, g1.w};
    float B1[4] = {u1.x, u1.y, u1.z, u1.w};
    float R2[4] = {r2.x, r2.y, r2.z, r2.w};
    float G2[4] = {g2.x, g2.y, g2.z, g2.w};
    float B2[4] = {u2.x, u2.y, u2.z, u2.w};

    float o[4];
#pragma unroll
    for (int pr = 0; pr < 2; pr++) {
        int j0 = pr * 2;
        float L1a, A1a, B1a, L2a, A2a, B2a;
        float L1b, A1b, B1b, L2b, A2b, B2b;
        rgb2lab(R1[j0],   G1[j0],   B1[j0],   L1a, A1a, B1a);
        rgb2lab(R1[j0+1], G1[j0+1], B1[j0+1], L1b, A1b, B1b);
        rgb2lab(R2[j0],   G2[j0],   B2[j0],   L2a, A2a, B2a);
        rgb2lab(R2[j0+1], G2[j0+1], B2[j0+1], L2b, A2b, B2b);

        u64 res = ciede_pair(pk2(L1a, L1b), pk2(A1a, A1b), pk2(B1a, B1b),
                             pk2(L2a, L2b), pk2(A2a, A2b), pk2(B2a, B2b));
        upk2(o[j0], o[j0 + 1], res);
    }

    out[v] = make_float4(o[0], o[1], o[2], o[3]);
}

// ---------------------------------------------------------------------------
// Launch
// ---------------------------------------------------------------------------
extern "C" void kernel_launch(void* const* d_in, const int* in_sizes, int n_in,
                              void* d_out, int out_size) {
    const float4* im1 = (const float4*)d_in[0];
    const float4* im2 = (const float4*)d_in[1];
    float4* out = (float4*)d_out;

    int nq = out_size >> 2;
    int blocks = (nq + 255) / 256;
    ciede2000_kernel<<<blocks, 256>>>(im1, im2, out, nq);
}